// round 14
// baseline (speedup 1.0000x reference)
#include <cuda_runtime.h>
#include <cuda_bf16.h>
#include <cstdint>
#include <math.h>

#define BB 4096
#define TT 200
#define EE 64

using u64 = unsigned long long;

// ---------------- device globals ----------------
__device__ float g_att[(size_t)BB * TT];            // softmax * mask, [B,T]
__device__ float g_xp[3ull * BB * TT * EE];         // xp = gru@W + b, [gate][b*T+t][e]
#define RT64 ((size_t)BB * TT * EE)

// ---------------- packed fp32x2 helpers ----------------
static __device__ __forceinline__ u64 pk2(float x, float y) {
    u64 r; asm("mov.b64 %0,{%1,%2};" : "=l"(r) : "f"(x), "f"(y)); return r;
}
static __device__ __forceinline__ float2 up2(u64 v) {
    float2 r; asm("mov.b64 {%0,%1},%2;" : "=f"(r.x), "=f"(r.y) : "l"(v)); return r;
}
static __device__ __forceinline__ void fma2(u64& d, u64 a, u64 b) {
    asm("fma.rn.f32x2 %0,%1,%2,%0;" : "+l"(d) : "l"(a), "l"(b));
}
static __device__ __forceinline__ void add2(u64& d, u64 a) {
    asm("add.rn.f32x2 %0,%0,%1;" : "+l"(d) : "l"(a));
}
static __device__ __forceinline__ float rcpa(float x) {
    float r; asm("rcp.approx.f32 %0, %1;" : "=f"(r) : "f"(x)); return r;
}
// two sigmoids sharing one MUFU.RCP (validated: rel_err 3.3e-7)
static __device__ __forceinline__ float2 sigmoid2(float a, float b) {
    float ea = __expf(-fabsf(a)), eb = __expf(-fabsf(b));
    float pa = 1.0f + ea, pb = 1.0f + eb;
    float R  = rcpa(pa * pb);
    float ia = pb * R, ib = pa * R;
    float sa = (a >= 0.0f) ? ia : ea * ia;
    float sb = (b >= 0.0f) ? ib : eb * ib;
    return make_float2(sa, sb);
}
// two tanhs sharing one MUFU.RCP (validated)
static __device__ __forceinline__ float2 tanh2(float a, float b) {
    float ea = __expf(-2.0f * fabsf(a)), eb = __expf(-2.0f * fabsf(b));
    float pa = 1.0f + ea, pb = 1.0f + eb;
    float R  = rcpa(pa * pb);
    float ta = (1.0f - ea) * pb * R, tb = (1.0f - eb) * pa * R;
    return make_float2(copysignf(ta, a), copysignf(tb, b));
}
static __device__ __forceinline__ void cp_async16(void* dst, const void* src) {
    unsigned s = (unsigned)__cvta_generic_to_shared(dst);
    asm volatile("cp.async.cg.shared.global [%0], [%1], 16;" :: "r"(s), "l"(src));
}
static __device__ __forceinline__ int load_mask(const void* mp, size_t idx, int u8) {
    return u8 ? (int)(((const unsigned char*)mp)[idx] != 0)
              : (int)(((const int*)mp)[idx] != 0);
}

// =====================================================================
// Kernel 1: attention + softmax, one CTA per b, 128 threads, 2 t/thread.
// (unchanged from R12: 258us)
// =====================================================================
__global__ __launch_bounds__(128, 3) void attn_kernel(
    const float* __restrict__ gru, const float* __restrict__ query,
    const void* __restrict__ maskp,
    const float* __restrict__ aw1, const float* __restrict__ ab1,
    const float* __restrict__ aw2, const float* __restrict__ ab2,
    const float* __restrict__ aw3, const float* __restrict__ ab3)
{
    extern __shared__ float sm[];
    float* q_s   = sm;
    float* qa_s  = sm + 64;
    float* Wk_s  = sm + 96;
    float* Wqk_s = Wk_s + 2048;
    float* aw2_s = Wqk_s + 2048;
    float* ab2_s = aw2_s + 512;
    float* aw3_s = ab2_s + 16;
    float* red_s = aw3_s + 16;
    float* Ks    = red_s + 16;

    int tid = threadIdx.x;
    int b   = blockIdx.x;

    if (tid < 32) {
        const unsigned int* mw = (const unsigned int*)maskp;
        unsigned bad = 0;
        #pragma unroll
        for (int i = 0; i < 16; i++) bad |= (mw[tid * 16 + i] > 1u) ? 1u : 0u;
        unsigned any = __any_sync(0xffffffffu, bad);
        if (tid == 0) red_s[12] = any ? 1.0f : 0.0f;
    }

    if (tid < 64) q_s[tid] = query[(size_t)b * EE + tid];
    for (int i = tid; i < 2048; i += 128) {
        int e = i >> 5, j = i & 31;
        Wk_s[i]  = aw1[(64 + e) * 32 + j] - aw1[(128 + e) * 32 + j];
        Wqk_s[i] = aw1[(192 + e) * 32 + j];
    }
    for (int i = tid; i < 512; i += 128) aw2_s[i] = aw2[i];
    if (tid < 16) { ab2_s[tid] = ab2[tid]; aw3_s[tid] = aw3[tid]; }
    for (int i = tid; i < TT * 16; i += 128) {
        int row = i >> 4, c = (i & 15) * 4;
        float4 v = *(const float4*)(gru + ((size_t)b * TT + row) * EE + c);
        float* d = Ks + row * 65 + c;
        d[0] = v.x; d[1] = v.y; d[2] = v.z; d[3] = v.w;
    }
    __syncthreads();

    if (tid < 32) {
        float s = ab1[tid];
        for (int e = 0; e < 64; e++)
            s += q_s[e] * (aw1[e * 32 + tid] + aw1[(128 + e) * 32 + tid]);
        qa_s[tid] = s;
    }
    __syncthreads();

    int mu8 = (red_s[12] != 0.0f);
    int t0 = tid;
    int t1 = tid + 128;
    bool v1 = (t1 < TT);
    int t1r = v1 ? t1 : t0;

    u64 acc0[16], acc1[16];
    const ulonglong2* Wk4  = (const ulonglong2*)Wk_s;
    const ulonglong2* Wqk4 = (const ulonglong2*)Wqk_s;
    #pragma unroll
    for (int j = 0; j < 16; j++) {
        u64 qa = pk2(qa_s[2 * j], qa_s[2 * j + 1]);
        acc0[j] = qa; acc1[j] = qa;
    }
    const float* kr0 = Ks + t0 * 65;
    const float* kr1 = Ks + t1r * 65;
    #pragma unroll 4
    for (int e = 0; e < 64; e++) {
        float qv  = q_s[e];
        float kv0 = kr0[e], kv1 = kr1[e];
        u64 k20 = pk2(kv0, kv0), q20 = pk2(qv * kv0, qv * kv0);
        u64 k21 = pk2(kv1, kv1), q21 = pk2(qv * kv1, qv * kv1);
        #pragma unroll
        for (int j2 = 0; j2 < 8; j2++) {
            ulonglong2 wa = Wk4[e * 8 + j2];
            ulonglong2 wb = Wqk4[e * 8 + j2];
            fma2(acc0[2 * j2],     k20, wa.x); fma2(acc0[2 * j2 + 1], k20, wa.y);
            fma2(acc0[2 * j2],     q20, wb.x); fma2(acc0[2 * j2 + 1], q20, wb.y);
            fma2(acc1[2 * j2],     k21, wa.x); fma2(acc1[2 * j2 + 1], k21, wa.y);
            fma2(acc1[2 * j2],     q21, wb.x); fma2(acc1[2 * j2 + 1], q21, wb.y);
        }
    }

    const ulonglong2* A24 = (const ulonglong2*)aw2_s;
    float lgt[2];
    #pragma unroll
    for (int which = 0; which < 2; which++) {
        u64* acc = which ? acc1 : acc0;
        u64 acc2[8];
        #pragma unroll
        for (int j = 0; j < 8; j++) acc2[j] = pk2(ab2_s[2 * j], ab2_s[2 * j + 1]);
        #pragma unroll
        for (int j = 0; j < 16; j++) {
            float2 v = up2(acc[j]);
            float2 h = sigmoid2(v.x, v.y);
            u64 ha = pk2(h.x, h.x), hb = pk2(h.y, h.y);
            #pragma unroll
            for (int j2 = 0; j2 < 4; j2++) {
                ulonglong2 wa = A24[(2 * j) * 4 + j2];
                fma2(acc2[2 * j2],     ha, wa.x);
                fma2(acc2[2 * j2 + 1], ha, wa.y);
                ulonglong2 wb = A24[(2 * j + 1) * 4 + j2];
                fma2(acc2[2 * j2],     hb, wb.x);
                fma2(acc2[2 * j2 + 1], hb, wb.y);
            }
        }
        float l = ab3[0];
        #pragma unroll
        for (int j = 0; j < 8; j++) {
            float2 v = up2(acc2[j]);
            float2 h = sigmoid2(v.x, v.y);
            l += h.x * aw3_s[2 * j] + h.y * aw3_s[2 * j + 1];
        }
        lgt[which] = l;
    }

    int m0 = load_mask(maskp, (size_t)b * TT + t0, mu8);
    int m1 = v1 ? load_mask(maskp, (size_t)b * TT + t1, mu8) : 0;
    float lg0 = m0 ? lgt[0] : -1.0e9f;
    float lg1 = v1 ? (m1 ? lgt[1] : -1.0e9f) : -3.0e38f;

    float v = fmaxf(lg0, lg1);
    #pragma unroll
    for (int off = 16; off > 0; off >>= 1) v = fmaxf(v, __shfl_xor_sync(0xffffffffu, v, off));
    if ((tid & 31) == 0) red_s[tid >> 5] = v;
    __syncthreads();
    if (tid == 0) { float m = red_s[0]; for (int i = 1; i < 4; i++) m = fmaxf(m, red_s[i]); red_s[8] = m; }
    __syncthreads();
    float bmax = red_s[8];
    float ex0 = __expf(lg0 - bmax);
    float ex1 = v1 ? __expf(lg1 - bmax) : 0.0f;
    float s = ex0 + ex1;
    #pragma unroll
    for (int off = 16; off > 0; off >>= 1) s += __shfl_xor_sync(0xffffffffu, s, off);
    if ((tid & 31) == 0) red_s[tid >> 5] = s;
    __syncthreads();
    if (tid == 0) { float m = 0.0f; for (int i = 0; i < 4; i++) m += red_s[i]; red_s[9] = m; }
    __syncthreads();
    float inv = __frcp_rn(red_s[9]);
    g_att[(size_t)b * TT + t0] = ex0 * inv * (m0 ? 1.0f : 0.0f);
    if (v1) g_att[(size_t)b * TT + t1] = ex1 * inv * (m1 ? 1.0f : 0.0f);
}

// =====================================================================
// Kernel 2: xp = gru@W + b (gate-split). Unchanged from R12.
// =====================================================================
#define XP_RPB 256
#define KT_S 36
__global__ __launch_bounds__(128) void xp_kernel(
    const float* __restrict__ gru, const float* __restrict__ W,
    const float* __restrict__ bias)
{
    extern __shared__ float sm[];
    float* Wr = sm;
    float* Wz = Wr + 64 * 66;
    float* Wn = Wz + 64 * 66;
    float* stage = Wn + 64 * 66;
    float* kT    = stage + 32 * 68;

    int tid = threadIdx.x, lane = tid & 31, wid = tid >> 5;
    size_t row0 = (size_t)blockIdx.x * XP_RPB;

    for (int i = tid; i < 64 * 64; i += 128) {
        int k = i >> 6, e = i & 63;
        const float* wrow = W + k * 192;
        Wr[k * 66 + e] = wrow[e];
        Wz[k * 66 + e] = wrow[64 + e];
        Wn[k * 66 + e] = wrow[128 + e];
    }

    int r = tid >> 2, c0 = (tid & 3) * 16;
    {
        const float* src = gru + (row0 + r) * EE + c0;
        float* dst = stage + r * 68 + c0;
        cp_async16(dst, src);      cp_async16(dst + 4, src + 4);
        cp_async16(dst + 8, src + 8); cp_async16(dst + 12, src + 12);
        asm volatile("cp.async.commit_group;");
    }

    u64 br = *(const u64*)(bias + 2 * lane);
    u64 bz = *(const u64*)(bias + 64 + 2 * lane);
    u64 bn = *(const u64*)(bias + 128 + 2 * lane);
    int r0 = wid * 8;

    for (int tile = 0; tile < XP_RPB / 32; tile++) {
        asm volatile("cp.async.wait_group 0;" ::: "memory");
        __syncthreads();

        {
            const float* srow = stage + r * 68 + c0;
            #pragma unroll
            for (int q = 0; q < 4; q++) {
                float4 v = *(const float4*)(srow + 4 * q);
                kT[(c0 + 4 * q + 0) * KT_S + r] = v.x;
                kT[(c0 + 4 * q + 1) * KT_S + r] = v.y;
                kT[(c0 + 4 * q + 2) * KT_S + r] = v.z;
                kT[(c0 + 4 * q + 3) * KT_S + r] = v.w;
            }
        }
        __syncthreads();

        if (tile + 1 < XP_RPB / 32) {
            const float* src = gru + (row0 + (tile + 1) * 32 + r) * EE + c0;
            float* dst = stage + r * 68 + c0;
            cp_async16(dst, src);      cp_async16(dst + 4, src + 4);
            cp_async16(dst + 8, src + 8); cp_async16(dst + 12, src + 12);
            asm volatile("cp.async.commit_group;");
        }

        u64 ar[8], az[8], an[8];
        #pragma unroll
        for (int rr = 0; rr < 8; rr++) { ar[rr] = br; az[rr] = bz; an[rr] = bn; }
        #pragma unroll 2
        for (int k = 0; k < 64; k++) {
            float4 k03 = *(const float4*)(kT + k * KT_S + r0);
            float4 k47 = *(const float4*)(kT + k * KT_S + r0 + 4);
            u64 wr = *(const u64*)(Wr + k * 66 + 2 * lane);
            u64 wz = *(const u64*)(Wz + k * 66 + 2 * lane);
            u64 wn = *(const u64*)(Wn + k * 66 + 2 * lane);
            float kv8[8] = {k03.x, k03.y, k03.z, k03.w, k47.x, k47.y, k47.z, k47.w};
            #pragma unroll
            for (int rr = 0; rr < 8; rr++) {
                u64 k2 = pk2(kv8[rr], kv8[rr]);
                fma2(ar[rr], k2, wr); fma2(az[rr], k2, wz); fma2(an[rr], k2, wn);
            }
        }
        #pragma unroll
        for (int rr = 0; rr < 8; rr++) {
            size_t row = row0 + tile * 32 + r0 + rr;
            *(u64*)(g_xp +            row * EE + 2 * lane) = ar[rr];
            *(u64*)(g_xp + RT64     + row * EE + 2 * lane) = az[rr];
            *(u64*)(g_xp + 2 * RT64 + row * EE + 2 * lane) = an[rr];
        }
    }
}

// =====================================================================
// Kernel 3: GRU scan, k-split. 128 CTAs x 512 thr (16 warps, 4/SMSP).
// Warp = (rowgroup rg = wid&3 -> rows 8rg..8rg+7, kgroup kg = wid>>2
// -> k in [16kg, 16kg+16)). Each warp accumulates 8 rows over its 16 k.
// Partial exchange via smem; warp epilogues rows 8rg+2kg .. +2.
// hT double-buffered (R12 layout), 2 barriers/step.
// =====================================================================
#define HT_S 36
__global__ __launch_bounds__(512, 1) void scan_kernel(
    const float* __restrict__ U, float* __restrict__ out)
{
    extern __shared__ float sm[];
    float* Ur   = sm;                    // [64][66] each
    float* Uz   = Ur + 64 * 66;
    float* Un   = Uz + 64 * 66;
    float* hT   = Un + 64 * 66;          // [2][64][36]
    u64*   pX   = (u64*)(hT + 2 * 64 * HT_S);  // [32 rows][3 gates][4 kg][32 lanes]
    float* attS = (float*)(pX + 32 * 3 * 4 * 32);  // [2][32]

    int tid = threadIdx.x, lane = tid & 31, wid = tid >> 5;
    int rg = wid & 3, kg = wid >> 2;
    int rb  = blockIdx.x * 32;

    for (int i = tid; i < 64 * 64; i += 512) {
        int k = i >> 6, e = i & 63;
        const float* urow = U + k * 192;
        Ur[k * 66 + e] = urow[e];
        Uz[k * 66 + e] = urow[64 + e];
        Un[k * 66 + e] = urow[128 + e];
    }
    for (int i = tid; i < 64 * HT_S; i += 512) hT[i] = 0.0f;   // buffer 0
    if (tid < 32) attS[tid] = g_att[(size_t)(rb + tid) * TT];
    __syncthreads();

    int ra = rg * 8;                 // accumulation rows ra..ra+7
    int re = ra + 2 * kg;            // this warp's 2 epilogue rows
    int k0 = kg * 16;                // this warp's k range

    float2 hreg[2];
    hreg[0] = make_float2(0.0f, 0.0f);
    hreg[1] = make_float2(0.0f, 0.0f);

    u64 xcr[2], xcz[2], xcn[2];
    #pragma unroll
    for (int i = 0; i < 2; i++) {
        size_t row = ((size_t)(rb + re + i) * TT) * EE + 2 * lane;   // t = 0
        xcr[i] = *(const u64*)(g_xp + row);
        xcz[i] = *(const u64*)(g_xp + RT64 + row);
        xcn[i] = *(const u64*)(g_xp + 2 * RT64 + row);
    }

    for (int t = 0; t < TT; t++) {
        int cur = t & 1, nxt = cur ^ 1;
        const float* hc = hT + cur * 64 * HT_S;
        float*       hw = hT + nxt * 64 * HT_S;

        u64 xnr[2], xnz[2], xnn[2];
        float aN = 0.0f;
        if (t + 1 < TT) {
            #pragma unroll
            for (int i = 0; i < 2; i++) {
                size_t row = ((size_t)(rb + re + i) * TT + (t + 1)) * EE + 2 * lane;
                xnr[i] = *(const u64*)(g_xp + row);
                xnz[i] = *(const u64*)(g_xp + RT64 + row);
                xnn[i] = *(const u64*)(g_xp + 2 * RT64 + row);
            }
            if (tid < 32) aN = g_att[(size_t)(rb + tid) * TT + t + 1];
        }

        u64 a2r[8], a2z[8], a2n[8];
        #pragma unroll
        for (int rr = 0; rr < 8; rr++) { a2r[rr] = 0ull; a2z[rr] = 0ull; a2n[rr] = 0ull; }

        #pragma unroll 4
        for (int kk = 0; kk < 16; kk++) {
            int k = k0 + kk;
            float4 h03 = *(const float4*)(hc + k * HT_S + ra);       // broadcast
            float4 h47 = *(const float4*)(hc + k * HT_S + ra + 4);   // broadcast
            u64 ur = *(const u64*)(Ur + k * 66 + 2 * lane);
            u64 uz = *(const u64*)(Uz + k * 66 + 2 * lane);
            u64 un = *(const u64*)(Un + k * 66 + 2 * lane);
            float hv8[8] = {h03.x, h03.y, h03.z, h03.w, h47.x, h47.y, h47.z, h47.w};
            #pragma unroll
            for (int rr = 0; rr < 8; rr++) {
                u64 h2 = pk2(hv8[rr], hv8[rr]);
                fma2(a2r[rr], h2, ur); fma2(a2z[rr], h2, uz); fma2(a2n[rr], h2, un);
            }
        }

        // store partials for the 6 rows this warp does NOT epilogue
        #pragma unroll
        for (int rr = 0; rr < 8; rr++) {
            if ((rr >> 1) != kg) {
                int row = ra + rr;
                pX[((row * 3 + 0) * 4 + kg) * 32 + lane] = a2r[rr];
                pX[((row * 3 + 1) * 4 + kg) * 32 + lane] = a2z[rr];
                pX[((row * 3 + 2) * 4 + kg) * 32 + lane] = a2n[rr];
            }
        }
        __syncthreads();   // partials visible; hc reads done

        // merge: own 2 rows get 3 partner partials each
        u64 mr[2], mz[2], mn[2];
        #pragma unroll
        for (int i = 0; i < 2; i++) {
            int rr = 2 * kg + i;
            int row = re + i;
            mr[i] = a2r[rr]; mz[i] = a2z[rr]; mn[i] = a2n[rr];
            #pragma unroll
            for (int kk = 0; kk < 4; kk++) {
                if (kk != kg) {
                    add2(mr[i], pX[((row * 3 + 0) * 4 + kk) * 32 + lane]);
                    add2(mz[i], pX[((row * 3 + 1) * 4 + kk) * 32 + lane]);
                    add2(mn[i], pX[((row * 3 + 2) * 4 + kk) * 32 + lane]);
                }
            }
        }

        // epilogue for 2 rows
        #pragma unroll
        for (int i = 0; i < 2; i++) {
            int row = re + i;
            float2 xr = up2(xcr[i]), xz = up2(xcz[i]), xn = up2(xcn[i]);
            float2 hr = up2(mr[i]), hz = up2(mz[i]), hn = up2(mn[i]);
            float av = attS[cur * 32 + row];      // mask already folded
            float2 hold = hreg[i];
            float2 rgt = sigmoid2(xr.x + hr.x, xr.y + hr.y);
            float2 zgt = sigmoid2(xz.x + hz.x, xz.y + hz.y);
            float2 ngt = tanh2(xn.x + rgt.x * hn.x, xn.y + rgt.y * hn.y);
            float zt0 = av * zgt.x, zt1 = av * zgt.y;
            hreg[i] = make_float2(hold.x + zt0 * (ngt.x - hold.x),
                                  hold.y + zt1 * (ngt.y - hold.y));
        }
        {   // transposed write of 2 adjacent rows: 2x STS.64 (float2)
            *(float2*)(hw + (2 * lane)     * HT_S + re) = make_float2(hreg[0].x, hreg[1].x);
            *(float2*)(hw + (2 * lane + 1) * HT_S + re) = make_float2(hreg[0].y, hreg[1].y);
        }
        if (t + 1 < TT) {
            if (tid < 32) attS[nxt * 32 + tid] = aN;
            #pragma unroll
            for (int i = 0; i < 2; i++) {
                xcr[i] = xnr[i]; xcz[i] = xnz[i]; xcn[i] = xnn[i];
            }
        }
        __syncthreads();   // hT[nxt]/attS[nxt] ready; pX reusable
    }

    #pragma unroll
    for (int i = 0; i < 2; i++) {
        *(float2*)(out + (size_t)(rb + re + i) * EE + 2 * lane) = hreg[i];
    }
}

// =====================================================================
extern "C" void kernel_launch(void* const* d_in, const int* in_sizes, int n_in,
                              void* d_out, int out_size) {
    const float* gru   = (const float*)d_in[0];
    const float* query = (const float*)d_in[1];
    const void*  maskp = (const void*) d_in[2];
    const float* aw1   = (const float*)d_in[3];
    const float* ab1   = (const float*)d_in[4];
    const float* aw2   = (const float*)d_in[5];
    const float* ab2   = (const float*)d_in[6];
    const float* aw3   = (const float*)d_in[7];
    const float* ab3   = (const float*)d_in[8];
    const float* W     = (const float*)d_in[9];
    const float* U     = (const float*)d_in[10];
    const float* bias  = (const float*)d_in[11];
    float* out = (float*)d_out;

    const int attn_smem = (64 + 32 + 2048 + 2048 + 512 + 16 + 16 + 16 + TT * 65) * 4;
    const int xp_smem   = (3 * 64 * 66 + 32 * 68 + 64 * KT_S) * 4;
    const int scan_smem = (3 * 64 * 66 + 2 * 64 * HT_S) * 4
                        + 32 * 3 * 4 * 32 * 8 + 64 * 4;
    cudaFuncSetAttribute(attn_kernel, cudaFuncAttributeMaxDynamicSharedMemorySize, attn_smem);
    cudaFuncSetAttribute(xp_kernel,   cudaFuncAttributeMaxDynamicSharedMemorySize, xp_smem);
    cudaFuncSetAttribute(scan_kernel, cudaFuncAttributeMaxDynamicSharedMemorySize, scan_smem);

    attn_kernel<<<BB, 128, attn_smem>>>(gru, query, maskp, aw1, ab1, aw2, ab2, aw3, ab3);
    xp_kernel<<<(BB * TT) / XP_RPB, 128, xp_smem>>>(gru, W, bias);
    scan_kernel<<<128, 512, scan_smem>>>(U, out);
}

// round 15
// speedup vs baseline: 1.3048x; 1.3048x over previous
#include <cuda_runtime.h>
#include <cuda_bf16.h>
#include <cstdint>
#include <math.h>

#define BB 4096
#define TT 200
#define EE 64

using u64 = unsigned long long;

// ---------------- device globals ----------------
__device__ float g_att[(size_t)BB * TT];            // softmax * mask, [B,T]
__device__ float g_xp[3ull * BB * TT * EE];         // xp = gru@W + b, [gate][b*T+t][e]
#define RT64 ((size_t)BB * TT * EE)

// ---------------- packed fp32x2 helpers ----------------
static __device__ __forceinline__ u64 pk2(float x, float y) {
    u64 r; asm("mov.b64 %0,{%1,%2};" : "=l"(r) : "f"(x), "f"(y)); return r;
}
static __device__ __forceinline__ float2 up2(u64 v) {
    float2 r; asm("mov.b64 {%0,%1},%2;" : "=f"(r.x), "=f"(r.y) : "l"(v)); return r;
}
static __device__ __forceinline__ void fma2(u64& d, u64 a, u64 b) {
    asm("fma.rn.f32x2 %0,%1,%2,%0;" : "+l"(d) : "l"(a), "l"(b));
}
static __device__ __forceinline__ float rcpa(float x) {
    float r; asm("rcp.approx.f32 %0, %1;" : "=f"(r) : "f"(x)); return r;
}
// two sigmoids sharing one MUFU.RCP (validated: rel_err 3.3e-7)
static __device__ __forceinline__ float2 sigmoid2(float a, float b) {
    float ea = __expf(-fabsf(a)), eb = __expf(-fabsf(b));
    float pa = 1.0f + ea, pb = 1.0f + eb;
    float R  = rcpa(pa * pb);
    float ia = pb * R, ib = pa * R;
    float sa = (a >= 0.0f) ? ia : ea * ia;
    float sb = (b >= 0.0f) ? ib : eb * ib;
    return make_float2(sa, sb);
}
// two tanhs sharing one MUFU.RCP (validated)
static __device__ __forceinline__ float2 tanh2(float a, float b) {
    float ea = __expf(-2.0f * fabsf(a)), eb = __expf(-2.0f * fabsf(b));
    float pa = 1.0f + ea, pb = 1.0f + eb;
    float R  = rcpa(pa * pb);
    float ta = (1.0f - ea) * pb * R, tb = (1.0f - eb) * pa * R;
    return make_float2(copysignf(ta, a), copysignf(tb, b));
}
static __device__ __forceinline__ void cp_async16(void* dst, const void* src) {
    unsigned s = (unsigned)__cvta_generic_to_shared(dst);
    asm volatile("cp.async.cg.shared.global [%0], [%1], 16;" :: "r"(s), "l"(src));
}
static __device__ __forceinline__ int load_mask(const void* mp, size_t idx, int u8) {
    return u8 ? (int)(((const unsigned char*)mp)[idx] != 0)
              : (int)(((const int*)mp)[idx] != 0);
}

// =====================================================================
// Kernel 1: attention + softmax, one CTA per b, 128 threads, 2 t/thread.
// (unchanged from R12: 258us)
// =====================================================================
__global__ __launch_bounds__(128, 3) void attn_kernel(
    const float* __restrict__ gru, const float* __restrict__ query,
    const void* __restrict__ maskp,
    const float* __restrict__ aw1, const float* __restrict__ ab1,
    const float* __restrict__ aw2, const float* __restrict__ ab2,
    const float* __restrict__ aw3, const float* __restrict__ ab3)
{
    extern __shared__ float sm[];
    float* q_s   = sm;
    float* qa_s  = sm + 64;
    float* Wk_s  = sm + 96;
    float* Wqk_s = Wk_s + 2048;
    float* aw2_s = Wqk_s + 2048;
    float* ab2_s = aw2_s + 512;
    float* aw3_s = ab2_s + 16;
    float* red_s = aw3_s + 16;
    float* Ks    = red_s + 16;

    int tid = threadIdx.x;
    int b   = blockIdx.x;

    if (tid < 32) {
        const unsigned int* mw = (const unsigned int*)maskp;
        unsigned bad = 0;
        #pragma unroll
        for (int i = 0; i < 16; i++) bad |= (mw[tid * 16 + i] > 1u) ? 1u : 0u;
        unsigned any = __any_sync(0xffffffffu, bad);
        if (tid == 0) red_s[12] = any ? 1.0f : 0.0f;
    }

    if (tid < 64) q_s[tid] = query[(size_t)b * EE + tid];
    for (int i = tid; i < 2048; i += 128) {
        int e = i >> 5, j = i & 31;
        Wk_s[i]  = aw1[(64 + e) * 32 + j] - aw1[(128 + e) * 32 + j];
        Wqk_s[i] = aw1[(192 + e) * 32 + j];
    }
    for (int i = tid; i < 512; i += 128) aw2_s[i] = aw2[i];
    if (tid < 16) { ab2_s[tid] = ab2[tid]; aw3_s[tid] = aw3[tid]; }
    for (int i = tid; i < TT * 16; i += 128) {
        int row = i >> 4, c = (i & 15) * 4;
        float4 v = *(const float4*)(gru + ((size_t)b * TT + row) * EE + c);
        float* d = Ks + row * 65 + c;
        d[0] = v.x; d[1] = v.y; d[2] = v.z; d[3] = v.w;
    }
    __syncthreads();

    if (tid < 32) {
        float s = ab1[tid];
        for (int e = 0; e < 64; e++)
            s += q_s[e] * (aw1[e * 32 + tid] + aw1[(128 + e) * 32 + tid]);
        qa_s[tid] = s;
    }
    __syncthreads();

    int mu8 = (red_s[12] != 0.0f);
    int t0 = tid;
    int t1 = tid + 128;
    bool v1 = (t1 < TT);
    int t1r = v1 ? t1 : t0;

    u64 acc0[16], acc1[16];
    const ulonglong2* Wk4  = (const ulonglong2*)Wk_s;
    const ulonglong2* Wqk4 = (const ulonglong2*)Wqk_s;
    #pragma unroll
    for (int j = 0; j < 16; j++) {
        u64 qa = pk2(qa_s[2 * j], qa_s[2 * j + 1]);
        acc0[j] = qa; acc1[j] = qa;
    }
    const float* kr0 = Ks + t0 * 65;
    const float* kr1 = Ks + t1r * 65;
    #pragma unroll 4
    for (int e = 0; e < 64; e++) {
        float qv  = q_s[e];
        float kv0 = kr0[e], kv1 = kr1[e];
        u64 k20 = pk2(kv0, kv0), q20 = pk2(qv * kv0, qv * kv0);
        u64 k21 = pk2(kv1, kv1), q21 = pk2(qv * kv1, qv * kv1);
        #pragma unroll
        for (int j2 = 0; j2 < 8; j2++) {
            ulonglong2 wa = Wk4[e * 8 + j2];
            ulonglong2 wb = Wqk4[e * 8 + j2];
            fma2(acc0[2 * j2],     k20, wa.x); fma2(acc0[2 * j2 + 1], k20, wa.y);
            fma2(acc0[2 * j2],     q20, wb.x); fma2(acc0[2 * j2 + 1], q20, wb.y);
            fma2(acc1[2 * j2],     k21, wa.x); fma2(acc1[2 * j2 + 1], k21, wa.y);
            fma2(acc1[2 * j2],     q21, wb.x); fma2(acc1[2 * j2 + 1], q21, wb.y);
        }
    }

    const ulonglong2* A24 = (const ulonglong2*)aw2_s;
    float lgt[2];
    #pragma unroll
    for (int which = 0; which < 2; which++) {
        u64* acc = which ? acc1 : acc0;
        u64 acc2[8];
        #pragma unroll
        for (int j = 0; j < 8; j++) acc2[j] = pk2(ab2_s[2 * j], ab2_s[2 * j + 1]);
        #pragma unroll
        for (int j = 0; j < 16; j++) {
            float2 v = up2(acc[j]);
            float2 h = sigmoid2(v.x, v.y);
            u64 ha = pk2(h.x, h.x), hb = pk2(h.y, h.y);
            #pragma unroll
            for (int j2 = 0; j2 < 4; j2++) {
                ulonglong2 wa = A24[(2 * j) * 4 + j2];
                fma2(acc2[2 * j2],     ha, wa.x);
                fma2(acc2[2 * j2 + 1], ha, wa.y);
                ulonglong2 wb = A24[(2 * j + 1) * 4 + j2];
                fma2(acc2[2 * j2],     hb, wb.x);
                fma2(acc2[2 * j2 + 1], hb, wb.y);
            }
        }
        float l = ab3[0];
        #pragma unroll
        for (int j = 0; j < 8; j++) {
            float2 v = up2(acc2[j]);
            float2 h = sigmoid2(v.x, v.y);
            l += h.x * aw3_s[2 * j] + h.y * aw3_s[2 * j + 1];
        }
        lgt[which] = l;
    }

    int m0 = load_mask(maskp, (size_t)b * TT + t0, mu8);
    int m1 = v1 ? load_mask(maskp, (size_t)b * TT + t1, mu8) : 0;
    float lg0 = m0 ? lgt[0] : -1.0e9f;
    float lg1 = v1 ? (m1 ? lgt[1] : -1.0e9f) : -3.0e38f;

    float v = fmaxf(lg0, lg1);
    #pragma unroll
    for (int off = 16; off > 0; off >>= 1) v = fmaxf(v, __shfl_xor_sync(0xffffffffu, v, off));
    if ((tid & 31) == 0) red_s[tid >> 5] = v;
    __syncthreads();
    if (tid == 0) { float m = red_s[0]; for (int i = 1; i < 4; i++) m = fmaxf(m, red_s[i]); red_s[8] = m; }
    __syncthreads();
    float bmax = red_s[8];
    float ex0 = __expf(lg0 - bmax);
    float ex1 = v1 ? __expf(lg1 - bmax) : 0.0f;
    float s = ex0 + ex1;
    #pragma unroll
    for (int off = 16; off > 0; off >>= 1) s += __shfl_xor_sync(0xffffffffu, s, off);
    if ((tid & 31) == 0) red_s[tid >> 5] = s;
    __syncthreads();
    if (tid == 0) { float m = 0.0f; for (int i = 0; i < 4; i++) m += red_s[i]; red_s[9] = m; }
    __syncthreads();
    float inv = __frcp_rn(red_s[9]);
    g_att[(size_t)b * TT + t0] = ex0 * inv * (m0 ? 1.0f : 0.0f);
    if (v1) g_att[(size_t)b * TT + t1] = ex1 * inv * (m1 ? 1.0f : 0.0f);
}

// =====================================================================
// Kernel 2: xp = gru@W + b (gate-split). Unchanged from R12.
// =====================================================================
#define XP_RPB 256
#define KT_S 36
__global__ __launch_bounds__(128) void xp_kernel(
    const float* __restrict__ gru, const float* __restrict__ W,
    const float* __restrict__ bias)
{
    extern __shared__ float sm[];
    float* Wr = sm;
    float* Wz = Wr + 64 * 66;
    float* Wn = Wz + 64 * 66;
    float* stage = Wn + 64 * 66;
    float* kT    = stage + 32 * 68;

    int tid = threadIdx.x, lane = tid & 31, wid = tid >> 5;
    size_t row0 = (size_t)blockIdx.x * XP_RPB;

    for (int i = tid; i < 64 * 64; i += 128) {
        int k = i >> 6, e = i & 63;
        const float* wrow = W + k * 192;
        Wr[k * 66 + e] = wrow[e];
        Wz[k * 66 + e] = wrow[64 + e];
        Wn[k * 66 + e] = wrow[128 + e];
    }

    int r = tid >> 2, c0 = (tid & 3) * 16;
    {
        const float* src = gru + (row0 + r) * EE + c0;
        float* dst = stage + r * 68 + c0;
        cp_async16(dst, src);      cp_async16(dst + 4, src + 4);
        cp_async16(dst + 8, src + 8); cp_async16(dst + 12, src + 12);
        asm volatile("cp.async.commit_group;");
    }

    u64 br = *(const u64*)(bias + 2 * lane);
    u64 bz = *(const u64*)(bias + 64 + 2 * lane);
    u64 bn = *(const u64*)(bias + 128 + 2 * lane);
    int r0 = wid * 8;

    for (int tile = 0; tile < XP_RPB / 32; tile++) {
        asm volatile("cp.async.wait_group 0;" ::: "memory");
        __syncthreads();

        {
            const float* srow = stage + r * 68 + c0;
            #pragma unroll
            for (int q = 0; q < 4; q++) {
                float4 v = *(const float4*)(srow + 4 * q);
                kT[(c0 + 4 * q + 0) * KT_S + r] = v.x;
                kT[(c0 + 4 * q + 1) * KT_S + r] = v.y;
                kT[(c0 + 4 * q + 2) * KT_S + r] = v.z;
                kT[(c0 + 4 * q + 3) * KT_S + r] = v.w;
            }
        }
        __syncthreads();

        if (tile + 1 < XP_RPB / 32) {
            const float* src = gru + (row0 + (tile + 1) * 32 + r) * EE + c0;
            float* dst = stage + r * 68 + c0;
            cp_async16(dst, src);      cp_async16(dst + 4, src + 4);
            cp_async16(dst + 8, src + 8); cp_async16(dst + 12, src + 12);
            asm volatile("cp.async.commit_group;");
        }

        u64 ar[8], az[8], an[8];
        #pragma unroll
        for (int rr = 0; rr < 8; rr++) { ar[rr] = br; az[rr] = bz; an[rr] = bn; }
        #pragma unroll 2
        for (int k = 0; k < 64; k++) {
            float4 k03 = *(const float4*)(kT + k * KT_S + r0);
            float4 k47 = *(const float4*)(kT + k * KT_S + r0 + 4);
            u64 wr = *(const u64*)(Wr + k * 66 + 2 * lane);
            u64 wz = *(const u64*)(Wz + k * 66 + 2 * lane);
            u64 wn = *(const u64*)(Wn + k * 66 + 2 * lane);
            float kv8[8] = {k03.x, k03.y, k03.z, k03.w, k47.x, k47.y, k47.z, k47.w};
            #pragma unroll
            for (int rr = 0; rr < 8; rr++) {
                u64 k2 = pk2(kv8[rr], kv8[rr]);
                fma2(ar[rr], k2, wr); fma2(az[rr], k2, wz); fma2(an[rr], k2, wn);
            }
        }
        #pragma unroll
        for (int rr = 0; rr < 8; rr++) {
            size_t row = row0 + tile * 32 + r0 + rr;
            *(u64*)(g_xp +            row * EE + 2 * lane) = ar[rr];
            *(u64*)(g_xp + RT64     + row * EE + 2 * lane) = az[rr];
            *(u64*)(g_xp + 2 * RT64 + row * EE + 2 * lane) = an[rr];
        }
    }
}

// =====================================================================
// Kernel 3: GRU scan. R12 inner loop UNCHANGED; scheduling split:
// 256 CTAs x 128 thr x 16 rows, 2 CTAs co-resident per SM. Independent
// CTAs fill each other's barrier/MUFU stalls. 4 warps x 4 rows,
// hT [2][64][20] double-buffered, single barrier per step.
// =====================================================================
#define HT_S 20
#define SROWS 16
__global__ __launch_bounds__(128, 2) void scan_kernel(
    const float* __restrict__ U, float* __restrict__ out)
{
    extern __shared__ float sm[];
    float* Ur   = sm;                    // [64][66] each
    float* Uz   = Ur + 64 * 66;
    float* Un   = Uz + 64 * 66;
    float* hT   = Un + 64 * 66;          // [2][64][20]
    float* attS = hT + 2 * 64 * HT_S;    // [2][16]

    int tid = threadIdx.x, lane = tid & 31, wid = tid >> 5;
    int rb  = blockIdx.x * SROWS;

    for (int i = tid; i < 64 * 64; i += 128) {
        int k = i >> 6, e = i & 63;
        const float* urow = U + k * 192;
        Ur[k * 66 + e] = urow[e];
        Uz[k * 66 + e] = urow[64 + e];
        Un[k * 66 + e] = urow[128 + e];
    }
    for (int i = tid; i < 64 * HT_S; i += 128) hT[i] = 0.0f;   // buffer 0
    if (tid < SROWS) attS[tid] = g_att[(size_t)(rb + tid) * TT];
    __syncthreads();

    int r0 = wid * 4;
    float2 hreg[4];
    #pragma unroll
    for (int rr = 0; rr < 4; rr++) hreg[rr] = make_float2(0.0f, 0.0f);

    u64 xcr[4], xcz[4], xcn[4];
    #pragma unroll
    for (int rr = 0; rr < 4; rr++) {
        size_t row = ((size_t)(rb + r0 + rr) * TT) * EE + 2 * lane;   // t = 0
        xcr[rr] = *(const u64*)(g_xp + row);
        xcz[rr] = *(const u64*)(g_xp + RT64 + row);
        xcn[rr] = *(const u64*)(g_xp + 2 * RT64 + row);
    }

    for (int t = 0; t < TT; t++) {
        int cur = t & 1, nxt = cur ^ 1;
        const float* hc = hT + cur * 64 * HT_S;
        float*       hw = hT + nxt * 64 * HT_S;

        u64 xnr[4], xnz[4], xnn[4];
        float aN = 0.0f;
        if (t + 1 < TT) {
            #pragma unroll
            for (int rr = 0; rr < 4; rr++) {
                size_t row = ((size_t)(rb + r0 + rr) * TT + (t + 1)) * EE + 2 * lane;
                xnr[rr] = *(const u64*)(g_xp + row);
                xnz[rr] = *(const u64*)(g_xp + RT64 + row);
                xnn[rr] = *(const u64*)(g_xp + 2 * RT64 + row);
            }
            if (tid < SROWS) aN = g_att[(size_t)(rb + tid) * TT + t + 1];
        }

        u64 a2r[4], a2z[4], a2n[4];
        #pragma unroll
        for (int rr = 0; rr < 4; rr++) { a2r[rr] = 0ull; a2z[rr] = 0ull; a2n[rr] = 0ull; }

        #pragma unroll 4
        for (int k = 0; k < 64; k++) {
            float4 h03 = *(const float4*)(hc + k * HT_S + r0);   // broadcast LDS.128
            u64 ur = *(const u64*)(Ur + k * 66 + 2 * lane);
            u64 uz = *(const u64*)(Uz + k * 66 + 2 * lane);
            u64 un = *(const u64*)(Un + k * 66 + 2 * lane);
            float hv4[4] = {h03.x, h03.y, h03.z, h03.w};
            #pragma unroll
            for (int rr = 0; rr < 4; rr++) {
                u64 h2 = pk2(hv4[rr], hv4[rr]);
                fma2(a2r[rr], h2, ur); fma2(a2z[rr], h2, uz); fma2(a2n[rr], h2, un);
            }
        }

        #pragma unroll
        for (int rr = 0; rr < 4; rr++) {
            int row = r0 + rr;
            float2 xr = up2(xcr[rr]), xz = up2(xcz[rr]), xn = up2(xcn[rr]);
            float2 hr = up2(a2r[rr]), hz = up2(a2z[rr]), hn = up2(a2n[rr]);
            float av = attS[cur * SROWS + row];   // mask already folded
            float2 hold = hreg[rr];
            float2 rg = sigmoid2(xr.x + hr.x, xr.y + hr.y);
            float2 zg = sigmoid2(xz.x + hz.x, xz.y + hz.y);
            float2 ng = tanh2(xn.x + rg.x * hn.x, xn.y + rg.y * hn.y);
            float zt0 = av * zg.x, zt1 = av * zg.y;
            hreg[rr] = make_float2(hold.x + zt0 * (ng.x - hold.x),
                                   hold.y + zt1 * (ng.y - hold.y));
        }
        {   // transposed write to the other buffer: 2x STS.128
            float4 vx = make_float4(hreg[0].x, hreg[1].x, hreg[2].x, hreg[3].x);
            float4 vy = make_float4(hreg[0].y, hreg[1].y, hreg[2].y, hreg[3].y);
            *(float4*)(hw + (2 * lane)     * HT_S + r0) = vx;
            *(float4*)(hw + (2 * lane + 1) * HT_S + r0) = vy;
        }
        if (t + 1 < TT) {
            if (tid < SROWS) attS[nxt * SROWS + tid] = aN;
            #pragma unroll
            for (int rr = 0; rr < 4; rr++) {
                xcr[rr] = xnr[rr]; xcz[rr] = xnz[rr]; xcn[rr] = xnn[rr];
            }
        }
        __syncthreads();   // single barrier: next buffer ready for t+1
    }

    #pragma unroll
    for (int rr = 0; rr < 4; rr++) {
        int row = r0 + rr;
        *(float2*)(out + (size_t)(rb + row) * EE + 2 * lane) = hreg[rr];
    }
}

// =====================================================================
extern "C" void kernel_launch(void* const* d_in, const int* in_sizes, int n_in,
                              void* d_out, int out_size) {
    const float* gru   = (const float*)d_in[0];
    const float* query = (const float*)d_in[1];
    const void*  maskp = (const void*) d_in[2];
    const float* aw1   = (const float*)d_in[3];
    const float* ab1   = (const float*)d_in[4];
    const float* aw2   = (const float*)d_in[5];
    const float* ab2   = (const float*)d_in[6];
    const float* aw3   = (const float*)d_in[7];
    const float* ab3   = (const float*)d_in[8];
    const float* W     = (const float*)d_in[9];
    const float* U     = (const float*)d_in[10];
    const float* bias  = (const float*)d_in[11];
    float* out = (float*)d_out;

    const int attn_smem = (64 + 32 + 2048 + 2048 + 512 + 16 + 16 + 16 + TT * 65) * 4;
    const int xp_smem   = (3 * 64 * 66 + 32 * 68 + 64 * KT_S) * 4;
    const int scan_smem = (3 * 64 * 66 + 2 * 64 * HT_S + 2 * SROWS) * 4;
    cudaFuncSetAttribute(attn_kernel, cudaFuncAttributeMaxDynamicSharedMemorySize, attn_smem);
    cudaFuncSetAttribute(xp_kernel,   cudaFuncAttributeMaxDynamicSharedMemorySize, xp_smem);
    cudaFuncSetAttribute(scan_kernel, cudaFuncAttributeMaxDynamicSharedMemorySize, scan_smem);

    attn_kernel<<<BB, 128, attn_smem>>>(gru, query, maskp, aw1, ab1, aw2, ab2, aw3, ab3);
    xp_kernel<<<(BB * TT) / XP_RPB, 128, xp_smem>>>(gru, W, bias);
    scan_kernel<<<BB / SROWS, 128, scan_smem>>>(U, out);
}

// round 17
// speedup vs baseline: 1.3321x; 1.0209x over previous
#include <cuda_runtime.h>
#include <cuda_bf16.h>
#include <cstdint>
#include <math.h>

#define BB 4096
#define TT 200
#define EE 64

using u64 = unsigned long long;

// ---------------- device globals ----------------
__device__ float g_att[(size_t)BB * TT];            // softmax * mask, [B,T]
__device__ float g_xp[3ull * BB * TT * EE];         // xp = gru@W + b, [gate][b*T+t][e]
#define RT64 ((size_t)BB * TT * EE)

// ---------------- packed fp32x2 helpers ----------------
static __device__ __forceinline__ u64 pk2(float x, float y) {
    u64 r; asm("mov.b64 %0,{%1,%2};" : "=l"(r) : "f"(x), "f"(y)); return r;
}
static __device__ __forceinline__ float2 up2(u64 v) {
    float2 r; asm("mov.b64 {%0,%1},%2;" : "=f"(r.x), "=f"(r.y) : "l"(v)); return r;
}
static __device__ __forceinline__ void fma2(u64& d, u64 a, u64 b) {
    asm("fma.rn.f32x2 %0,%1,%2,%0;" : "+l"(d) : "l"(a), "l"(b));
}
static __device__ __forceinline__ float rcpa(float x) {
    float r; asm("rcp.approx.f32 %0, %1;" : "=f"(r) : "f"(x)); return r;
}
// two sigmoids sharing one MUFU.RCP (validated: rel_err 3.3e-7)
static __device__ __forceinline__ float2 sigmoid2(float a, float b) {
    float ea = __expf(-fabsf(a)), eb = __expf(-fabsf(b));
    float pa = 1.0f + ea, pb = 1.0f + eb;
    float R  = rcpa(pa * pb);
    float ia = pb * R, ib = pa * R;
    float sa = (a >= 0.0f) ? ia : ea * ia;
    float sb = (b >= 0.0f) ? ib : eb * ib;
    return make_float2(sa, sb);
}
// two tanhs sharing one MUFU.RCP (validated)
static __device__ __forceinline__ float2 tanh2(float a, float b) {
    float ea = __expf(-2.0f * fabsf(a)), eb = __expf(-2.0f * fabsf(b));
    float pa = 1.0f + ea, pb = 1.0f + eb;
    float R  = rcpa(pa * pb);
    float ta = (1.0f - ea) * pb * R, tb = (1.0f - eb) * pa * R;
    return make_float2(copysignf(ta, a), copysignf(tb, b));
}
static __device__ __forceinline__ void cp_async16(void* dst, const void* src) {
    unsigned s = (unsigned)__cvta_generic_to_shared(dst);
    asm volatile("cp.async.cg.shared.global [%0], [%1], 16;" :: "r"(s), "l"(src));
}
static __device__ __forceinline__ int load_mask(const void* mp, size_t idx, int u8) {
    return u8 ? (int)(((const unsigned char*)mp)[idx] != 0)
              : (int)(((const int*)mp)[idx] != 0);
}

// =====================================================================
// Kernel 1: attention + softmax, one CTA per b, 128 threads, 2 t/thread.
// (unchanged from R12: 258us)
// =====================================================================
__global__ __launch_bounds__(128, 3) void attn_kernel(
    const float* __restrict__ gru, const float* __restrict__ query,
    const void* __restrict__ maskp,
    const float* __restrict__ aw1, const float* __restrict__ ab1,
    const float* __restrict__ aw2, const float* __restrict__ ab2,
    const float* __restrict__ aw3, const float* __restrict__ ab3)
{
    extern __shared__ float sm[];
    float* q_s   = sm;
    float* qa_s  = sm + 64;
    float* Wk_s  = sm + 96;
    float* Wqk_s = Wk_s + 2048;
    float* aw2_s = Wqk_s + 2048;
    float* ab2_s = aw2_s + 512;
    float* aw3_s = ab2_s + 16;
    float* red_s = aw3_s + 16;
    float* Ks    = red_s + 16;

    int tid = threadIdx.x;
    int b   = blockIdx.x;

    if (tid < 32) {
        const unsigned int* mw = (const unsigned int*)maskp;
        unsigned bad = 0;
        #pragma unroll
        for (int i = 0; i < 16; i++) bad |= (mw[tid * 16 + i] > 1u) ? 1u : 0u;
        unsigned any = __any_sync(0xffffffffu, bad);
        if (tid == 0) red_s[12] = any ? 1.0f : 0.0f;
    }

    if (tid < 64) q_s[tid] = query[(size_t)b * EE + tid];
    for (int i = tid; i < 2048; i += 128) {
        int e = i >> 5, j = i & 31;
        Wk_s[i]  = aw1[(64 + e) * 32 + j] - aw1[(128 + e) * 32 + j];
        Wqk_s[i] = aw1[(192 + e) * 32 + j];
    }
    for (int i = tid; i < 512; i += 128) aw2_s[i] = aw2[i];
    if (tid < 16) { ab2_s[tid] = ab2[tid]; aw3_s[tid] = aw3[tid]; }
    for (int i = tid; i < TT * 16; i += 128) {
        int row = i >> 4, c = (i & 15) * 4;
        float4 v = *(const float4*)(gru + ((size_t)b * TT + row) * EE + c);
        float* d = Ks + row * 65 + c;
        d[0] = v.x; d[1] = v.y; d[2] = v.z; d[3] = v.w;
    }
    __syncthreads();

    if (tid < 32) {
        float s = ab1[tid];
        for (int e = 0; e < 64; e++)
            s += q_s[e] * (aw1[e * 32 + tid] + aw1[(128 + e) * 32 + tid]);
        qa_s[tid] = s;
    }
    __syncthreads();

    int mu8 = (red_s[12] != 0.0f);
    int t0 = tid;
    int t1 = tid + 128;
    bool v1 = (t1 < TT);
    int t1r = v1 ? t1 : t0;

    u64 acc0[16], acc1[16];
    const ulonglong2* Wk4  = (const ulonglong2*)Wk_s;
    const ulonglong2* Wqk4 = (const ulonglong2*)Wqk_s;
    #pragma unroll
    for (int j = 0; j < 16; j++) {
        u64 qa = pk2(qa_s[2 * j], qa_s[2 * j + 1]);
        acc0[j] = qa; acc1[j] = qa;
    }
    const float* kr0 = Ks + t0 * 65;
    const float* kr1 = Ks + t1r * 65;
    #pragma unroll 4
    for (int e = 0; e < 64; e++) {
        float qv  = q_s[e];
        float kv0 = kr0[e], kv1 = kr1[e];
        u64 k20 = pk2(kv0, kv0), q20 = pk2(qv * kv0, qv * kv0);
        u64 k21 = pk2(kv1, kv1), q21 = pk2(qv * kv1, qv * kv1);
        #pragma unroll
        for (int j2 = 0; j2 < 8; j2++) {
            ulonglong2 wa = Wk4[e * 8 + j2];
            ulonglong2 wb = Wqk4[e * 8 + j2];
            fma2(acc0[2 * j2],     k20, wa.x); fma2(acc0[2 * j2 + 1], k20, wa.y);
            fma2(acc0[2 * j2],     q20, wb.x); fma2(acc0[2 * j2 + 1], q20, wb.y);
            fma2(acc1[2 * j2],     k21, wa.x); fma2(acc1[2 * j2 + 1], k21, wa.y);
            fma2(acc1[2 * j2],     q21, wb.x); fma2(acc1[2 * j2 + 1], q21, wb.y);
        }
    }

    const ulonglong2* A24 = (const ulonglong2*)aw2_s;
    float lgt[2];
    #pragma unroll
    for (int which = 0; which < 2; which++) {
        u64* acc = which ? acc1 : acc0;
        u64 acc2[8];
        #pragma unroll
        for (int j = 0; j < 8; j++) acc2[j] = pk2(ab2_s[2 * j], ab2_s[2 * j + 1]);
        #pragma unroll
        for (int j = 0; j < 16; j++) {
            float2 v = up2(acc[j]);
            float2 h = sigmoid2(v.x, v.y);
            u64 ha = pk2(h.x, h.x), hb = pk2(h.y, h.y);
            #pragma unroll
            for (int j2 = 0; j2 < 4; j2++) {
                ulonglong2 wa = A24[(2 * j) * 4 + j2];
                fma2(acc2[2 * j2],     ha, wa.x);
                fma2(acc2[2 * j2 + 1], ha, wa.y);
                ulonglong2 wb = A24[(2 * j + 1) * 4 + j2];
                fma2(acc2[2 * j2],     hb, wb.x);
                fma2(acc2[2 * j2 + 1], hb, wb.y);
            }
        }
        float l = ab3[0];
        #pragma unroll
        for (int j = 0; j < 8; j++) {
            float2 v = up2(acc2[j]);
            float2 h = sigmoid2(v.x, v.y);
            l += h.x * aw3_s[2 * j] + h.y * aw3_s[2 * j + 1];
        }
        lgt[which] = l;
    }

    int m0 = load_mask(maskp, (size_t)b * TT + t0, mu8);
    int m1 = v1 ? load_mask(maskp, (size_t)b * TT + t1, mu8) : 0;
    float lg0 = m0 ? lgt[0] : -1.0e9f;
    float lg1 = v1 ? (m1 ? lgt[1] : -1.0e9f) : -3.0e38f;

    float v = fmaxf(lg0, lg1);
    #pragma unroll
    for (int off = 16; off > 0; off >>= 1) v = fmaxf(v, __shfl_xor_sync(0xffffffffu, v, off));
    if ((tid & 31) == 0) red_s[tid >> 5] = v;
    __syncthreads();
    if (tid == 0) { float m = red_s[0]; for (int i = 1; i < 4; i++) m = fmaxf(m, red_s[i]); red_s[8] = m; }
    __syncthreads();
    float bmax = red_s[8];
    float ex0 = __expf(lg0 - bmax);
    float ex1 = v1 ? __expf(lg1 - bmax) : 0.0f;
    float s = ex0 + ex1;
    #pragma unroll
    for (int off = 16; off > 0; off >>= 1) s += __shfl_xor_sync(0xffffffffu, s, off);
    if ((tid & 31) == 0) red_s[tid >> 5] = s;
    __syncthreads();
    if (tid == 0) { float m = 0.0f; for (int i = 0; i < 4; i++) m += red_s[i]; red_s[9] = m; }
    __syncthreads();
    float inv = __frcp_rn(red_s[9]);
    g_att[(size_t)b * TT + t0] = ex0 * inv * (m0 ? 1.0f : 0.0f);
    if (v1) g_att[(size_t)b * TT + t1] = ex1 * inv * (m1 ? 1.0f : 0.0f);
}

// =====================================================================
// Kernel 2: xp = gru@W + b (gate-split). Unchanged from R12.
// =====================================================================
#define XP_RPB 256
#define KT_S 36
__global__ __launch_bounds__(128) void xp_kernel(
    const float* __restrict__ gru, const float* __restrict__ W,
    const float* __restrict__ bias)
{
    extern __shared__ float sm[];
    float* Wr = sm;
    float* Wz = Wr + 64 * 66;
    float* Wn = Wz + 64 * 66;
    float* stage = Wn + 64 * 66;
    float* kT    = stage + 32 * 68;

    int tid = threadIdx.x, lane = tid & 31, wid = tid >> 5;
    size_t row0 = (size_t)blockIdx.x * XP_RPB;

    for (int i = tid; i < 64 * 64; i += 128) {
        int k = i >> 6, e = i & 63;
        const float* wrow = W + k * 192;
        Wr[k * 66 + e] = wrow[e];
        Wz[k * 66 + e] = wrow[64 + e];
        Wn[k * 66 + e] = wrow[128 + e];
    }

    int r = tid >> 2, c0 = (tid & 3) * 16;
    {
        const float* src = gru + (row0 + r) * EE + c0;
        float* dst = stage + r * 68 + c0;
        cp_async16(dst, src);      cp_async16(dst + 4, src + 4);
        cp_async16(dst + 8, src + 8); cp_async16(dst + 12, src + 12);
        asm volatile("cp.async.commit_group;");
    }

    u64 br = *(const u64*)(bias + 2 * lane);
    u64 bz = *(const u64*)(bias + 64 + 2 * lane);
    u64 bn = *(const u64*)(bias + 128 + 2 * lane);
    int r0 = wid * 8;

    for (int tile = 0; tile < XP_RPB / 32; tile++) {
        asm volatile("cp.async.wait_group 0;" ::: "memory");
        __syncthreads();

        {
            const float* srow = stage + r * 68 + c0;
            #pragma unroll
            for (int q = 0; q < 4; q++) {
                float4 v = *(const float4*)(srow + 4 * q);
                kT[(c0 + 4 * q + 0) * KT_S + r] = v.x;
                kT[(c0 + 4 * q + 1) * KT_S + r] = v.y;
                kT[(c0 + 4 * q + 2) * KT_S + r] = v.z;
                kT[(c0 + 4 * q + 3) * KT_S + r] = v.w;
            }
        }
        __syncthreads();

        if (tile + 1 < XP_RPB / 32) {
            const float* src = gru + (row0 + (tile + 1) * 32 + r) * EE + c0;
            float* dst = stage + r * 68 + c0;
            cp_async16(dst, src);      cp_async16(dst + 4, src + 4);
            cp_async16(dst + 8, src + 8); cp_async16(dst + 12, src + 12);
            asm volatile("cp.async.commit_group;");
        }

        u64 ar[8], az[8], an[8];
        #pragma unroll
        for (int rr = 0; rr < 8; rr++) { ar[rr] = br; az[rr] = bz; an[rr] = bn; }
        #pragma unroll 2
        for (int k = 0; k < 64; k++) {
            float4 k03 = *(const float4*)(kT + k * KT_S + r0);
            float4 k47 = *(const float4*)(kT + k * KT_S + r0 + 4);
            u64 wr = *(const u64*)(Wr + k * 66 + 2 * lane);
            u64 wz = *(const u64*)(Wz + k * 66 + 2 * lane);
            u64 wn = *(const u64*)(Wn + k * 66 + 2 * lane);
            float kv8[8] = {k03.x, k03.y, k03.z, k03.w, k47.x, k47.y, k47.z, k47.w};
            #pragma unroll
            for (int rr = 0; rr < 8; rr++) {
                u64 k2 = pk2(kv8[rr], kv8[rr]);
                fma2(ar[rr], k2, wr); fma2(az[rr], k2, wz); fma2(an[rr], k2, wn);
            }
        }
        #pragma unroll
        for (int rr = 0; rr < 8; rr++) {
            size_t row = row0 + tile * 32 + r0 + rr;
            *(u64*)(g_xp +            row * EE + 2 * lane) = ar[rr];
            *(u64*)(g_xp + RT64     + row * EE + 2 * lane) = az[rr];
            *(u64*)(g_xp + 2 * RT64 + row * EE + 2 * lane) = an[rr];
        }
    }
}

// =====================================================================
// Kernel 3: GRU scan — BARRIER-FREE. 256 CTAs x 128 thr x 16 rows,
// 2 CTAs/SM. Warp w owns rows 4w..4w+3: its hT region [all e][own 4
// cols] is warp-private (reads AND writes), so warps run independently;
// only __syncwarp() per step (cross-lane smem ordering). att values
// loaded per-warp from g_att (broadcast LDG, prefetched).
// =====================================================================
#define HT_S 20
#define SROWS 16
__global__ __launch_bounds__(128, 2) void scan_kernel(
    const float* __restrict__ U, float* __restrict__ out)
{
    extern __shared__ float sm[];
    float* Ur = sm;                  // [64][66] each
    float* Uz = Ur + 64 * 66;
    float* Un = Uz + 64 * 66;
    float* hT = Un + 64 * 66;        // [64][20] single buffer (warp-private cols)

    int tid = threadIdx.x, lane = tid & 31, wid = tid >> 5;
    int rb  = blockIdx.x * SROWS;

    for (int i = tid; i < 64 * 64; i += 128) {
        int k = i >> 6, e = i & 63;
        const float* urow = U + k * 192;
        Ur[k * 66 + e] = urow[e];
        Uz[k * 66 + e] = urow[64 + e];
        Un[k * 66 + e] = urow[128 + e];
    }
    for (int i = tid; i < 64 * HT_S; i += 128) hT[i] = 0.0f;
    __syncthreads();                 // weights + hT ready (only CTA-wide sync)

    int r0 = wid * 4;
    float2 hreg[4];
    float  avC[4], avN[4];
    #pragma unroll
    for (int rr = 0; rr < 4; rr++) {
        hreg[rr] = make_float2(0.0f, 0.0f);
        avC[rr]  = __ldg(g_att + (size_t)(rb + r0 + rr) * TT);   // t = 0 (broadcast)
    }

    u64 xcr[4], xcz[4], xcn[4];
    #pragma unroll
    for (int rr = 0; rr < 4; rr++) {
        size_t row = ((size_t)(rb + r0 + rr) * TT) * EE + 2 * lane;   // t = 0
        xcr[rr] = *(const u64*)(g_xp + row);
        xcz[rr] = *(const u64*)(g_xp + RT64 + row);
        xcn[rr] = *(const u64*)(g_xp + 2 * RT64 + row);
    }

    for (int t = 0; t < TT; t++) {
        u64 xnr[4], xnz[4], xnn[4];
        if (t + 1 < TT) {
            #pragma unroll
            for (int rr = 0; rr < 4; rr++) {
                size_t row = ((size_t)(rb + r0 + rr) * TT + (t + 1)) * EE + 2 * lane;
                xnr[rr] = *(const u64*)(g_xp + row);
                xnz[rr] = *(const u64*)(g_xp + RT64 + row);
                xnn[rr] = *(const u64*)(g_xp + 2 * RT64 + row);
                avN[rr] = __ldg(g_att + (size_t)(rb + r0 + rr) * TT + t + 1);
            }
        }

        u64 a2r[4], a2z[4], a2n[4];
        #pragma unroll
        for (int rr = 0; rr < 4; rr++) { a2r[rr] = 0ull; a2z[rr] = 0ull; a2n[rr] = 0ull; }

        #pragma unroll 4
        for (int k = 0; k < 64; k++) {
            float4 h03 = *(const float4*)(hT + k * HT_S + r0);   // broadcast LDS.128
            u64 ur = *(const u64*)(Ur + k * 66 + 2 * lane);
            u64 uz = *(const u64*)(Uz + k * 66 + 2 * lane);
            u64 un = *(const u64*)(Un + k * 66 + 2 * lane);
            float hv4[4] = {h03.x, h03.y, h03.z, h03.w};
            #pragma unroll
            for (int rr = 0; rr < 4; rr++) {
                u64 h2 = pk2(hv4[rr], hv4[rr]);
                fma2(a2r[rr], h2, ur); fma2(a2z[rr], h2, uz); fma2(a2n[rr], h2, un);
            }
        }

        #pragma unroll
        for (int rr = 0; rr < 4; rr++) {
            float2 xr = up2(xcr[rr]), xz = up2(xcz[rr]), xn = up2(xcn[rr]);
            float2 hr = up2(a2r[rr]), hz = up2(a2z[rr]), hn = up2(a2n[rr]);
            float av = avC[rr];                   // mask already folded
            float2 hold = hreg[rr];
            float2 rg = sigmoid2(xr.x + hr.x, xr.y + hr.y);
            float2 zg = sigmoid2(xz.x + hz.x, xz.y + hz.y);
            float2 ng = tanh2(xn.x + rg.x * hn.x, xn.y + rg.y * hn.y);
            float zt0 = av * zg.x, zt1 = av * zg.y;
            hreg[rr] = make_float2(hold.x + zt0 * (ng.x - hold.x),
                                   hold.y + zt1 * (ng.y - hold.y));
        }
        {   // transposed write into own columns: 2x STS.128
            float4 vx = make_float4(hreg[0].x, hreg[1].x, hreg[2].x, hreg[3].x);
            float4 vy = make_float4(hreg[0].y, hreg[1].y, hreg[2].y, hreg[3].y);
            *(float4*)(hT + (2 * lane)     * HT_S + r0) = vx;
            *(float4*)(hT + (2 * lane + 1) * HT_S + r0) = vy;
        }
        if (t + 1 < TT) {
            #pragma unroll
            for (int rr = 0; rr < 4; rr++) {
                xcr[rr] = xnr[rr]; xcz[rr] = xnz[rr]; xcn[rr] = xnn[rr];
                avC[rr] = avN[rr];
            }
        }
        __syncwarp();      // order this step's writes before next step's
                           // cross-lane reads (warp-private region)
    }

    #pragma unroll
    for (int rr = 0; rr < 4; rr++) {
        int row = r0 + rr;
        *(float2*)(out + (size_t)(rb + row) * EE + 2 * lane) = hreg[rr];
    }
}

// =====================================================================
extern "C" void kernel_launch(void* const* d_in, const int* in_sizes, int n_in,
                              void* d_out, int out_size) {
    const float* gru   = (const float*)d_in[0];
    const float* query = (const float*)d_in[1];
    const void*  maskp = (const void*) d_in[2];
    const float* aw1   = (const float*)d_in[3];
    const float* ab1   = (const float*)d_in[4];
    const float* aw2   = (const float*)d_in[5];
    const float* ab2   = (const float*)d_in[6];
    const float* aw3   = (const float*)d_in[7];
    const float* ab3   = (const float*)d_in[8];
    const float* W     = (const float*)d_in[9];
    const float* U     = (const float*)d_in[10];
    const float* bias  = (const float*)d_in[11];
    float* out = (float*)d_out;

    const int attn_smem = (64 + 32 + 2048 + 2048 + 512 + 16 + 16 + 16 + TT * 65) * 4;
    const int xp_smem   = (3 * 64 * 66 + 32 * 68 + 64 * KT_S) * 4;
    const int scan_smem = (3 * 64 * 66 + 64 * HT_S) * 4;
    cudaFuncSetAttribute(attn_kernel, cudaFuncAttributeMaxDynamicSharedMemorySize, attn_smem);
    cudaFuncSetAttribute(xp_kernel,   cudaFuncAttributeMaxDynamicSharedMemorySize, xp_smem);
    cudaFuncSetAttribute(scan_kernel, cudaFuncAttributeMaxDynamicSharedMemorySize, scan_smem);

    attn_kernel<<<BB, 128, attn_smem>>>(gru, query, maskp, aw1, ab1, aw2, ab2, aw3, ab3);
    xp_kernel<<<(BB * TT) / XP_RPB, 128, xp_smem>>>(gru, W, bias);
    scan_kernel<<<BB / SROWS, 128, scan_smem>>>(U, out);
}